// round 10
// baseline (speedup 1.0000x reference)
#include <cuda_runtime.h>
#include <cuda_bf16.h>
#include <cstdint>

#define BB   32
#define CC   128
#define HH   56
#define WW   56
#define HWS  (HH*WW)          // 3136
#define NPIX (BB*HWS)         // 100352
#define NELT (NPIX*CC)        // 12845056

// padded spatial layout: 58x58 per image (zero ring) + guard rows front/back
#define HP    58
#define PIMG  (HP*HP)         // 3364
#define GUARD 192             // guard rows (128 ch each) for tap shifts / tile overflow
#define NTILE 27              // ceil(3364/128)
#define NCTA  (BB*NTILE)      // 864 conv CTAs (also stats slots)
#define TAPB  32768           // one 128(pix|co) x 128(ci) bf16 tile
#define CONV_SMEM (4*TAPB + 2048)   // 2 stages x (A+B) + stats = 133120

// ----------------------------- scratch (device globals: no runtime allocs) --
__device__ __nv_bfloat16 g_apad[((size_t)GUARD + (size_t)BB*PIMG + GUARD) * CC]; // padded acts bf16
__device__ float         g_y[NELT];           // conv output, compact NHWC fp32
__device__ __nv_bfloat16 g_w1q[9*CC*CC];      // [tap][co][ci] bf16 (quantized ints)
__device__ __nv_bfloat16 g_w2q[9*CC*CC];
__device__ unsigned      g_sx_bits;
__device__ float         g_sw1, g_sw2, g_sa1;
__device__ float         g_bnA[2*CC], g_bnB[2*CC];
__device__ float         g_psum[NCTA*CC], g_psum2[NCTA*CC];
__device__ float         g_pmin[NCTA*CC], g_pmax[NCTA*CC];

// --------------------------------------------------------------- PTX glue --
__device__ __forceinline__ uint32_t smem_u32(const void* p) {
    uint32_t a;
    asm("{ .reg .u64 t; cvta.to.shared.u64 t, %1; cvt.u32.u64 %0, t; }" : "=r"(a) : "l"(p));
    return a;
}
__device__ __forceinline__ void cpasync16(uint32_t dst, const void* src) {
    asm volatile("cp.async.cg.shared.global [%0], [%1], 16;" :: "r"(dst), "l"(src));
}
#define CP_COMMIT() asm volatile("cp.async.commit_group;" ::: "memory")
#define CP_WAIT0()  asm volatile("cp.async.wait_group 0;" ::: "memory")
#define CP_WAIT1()  asm volatile("cp.async.wait_group 1;" ::: "memory")

__device__ __forceinline__ void ldsm_x4(uint32_t& r0, uint32_t& r1, uint32_t& r2, uint32_t& r3,
                                        uint32_t addr) {
    asm volatile("ldmatrix.sync.aligned.m8n8.x4.shared.b16 {%0,%1,%2,%3}, [%4];"
                 : "=r"(r0), "=r"(r1), "=r"(r2), "=r"(r3) : "r"(addr));
}
__device__ __forceinline__ void mma_bf16(float* c, const uint32_t* a, const uint32_t* b) {
    asm volatile("mma.sync.aligned.m16n8k16.row.col.f32.bf16.bf16.f32 "
                 "{%0,%1,%2,%3}, {%4,%5,%6,%7}, {%8,%9}, {%0,%1,%2,%3};"
                 : "+f"(c[0]), "+f"(c[1]), "+f"(c[2]), "+f"(c[3])
                 : "r"(a[0]), "r"(a[1]), "r"(a[2]), "r"(a[3]), "r"(b[0]), "r"(b[1]));
}
// order-invariant float<->uint encodings for atomic min/max
__device__ __forceinline__ unsigned encf(float f) {
    unsigned b = __float_as_uint(f);
    return (b & 0x80000000u) ? ~b : (b | 0x80000000u);
}
__device__ __forceinline__ float decf(unsigned u) {
    return __uint_as_float((u & 0x80000000u) ? (u & 0x7FFFFFFFu) : ~u);
}

// ----------------------------------------------------------------- helpers --
__global__ void k_zero() { g_sx_bits = 0u; }

__global__ void k_absmax_x(const float* __restrict__ x) {
    float m = 0.f;
    for (int i = blockIdx.x*blockDim.x + threadIdx.x; i < NELT; i += gridDim.x*blockDim.x)
        m = fmaxf(m, fabsf(x[i]));
    #pragma unroll
    for (int o = 16; o; o >>= 1) m = fmaxf(m, __shfl_xor_sync(0xffffffffu, m, o));
    __shared__ float s[32];
    int w = threadIdx.x >> 5, l = threadIdx.x & 31;
    if (l == 0) s[w] = m;
    __syncthreads();
    if (w == 0) {
        m = (l < (blockDim.x >> 5)) ? s[l] : 0.f;
        #pragma unroll
        for (int o = 16; o; o >>= 1) m = fmaxf(m, __shfl_xor_sync(0xffffffffu, m, o));
        if (l == 0) atomicMax(&g_sx_bits, __float_as_uint(m));
    }
}

__global__ void k_absmax_w(const float* __restrict__ w1, const float* __restrict__ w2) {
    const float* w = blockIdx.x ? w2 : w1;
    float m = 0.f;
    for (int i = threadIdx.x; i < CC*CC*9; i += blockDim.x) m = fmaxf(m, fabsf(w[i]));
    #pragma unroll
    for (int o = 16; o; o >>= 1) m = fmaxf(m, __shfl_xor_sync(0xffffffffu, m, o));
    __shared__ float s[32];
    int wi = threadIdx.x >> 5, l = threadIdx.x & 31;
    if (l == 0) s[wi] = m;
    __syncthreads();
    if (wi == 0) {
        m = (l < (blockDim.x >> 5)) ? s[l] : 0.f;
        #pragma unroll
        for (int o = 16; o; o >>= 1) m = fmaxf(m, __shfl_xor_sync(0xffffffffu, m, o));
        if (l == 0) { float sc = m + 1e-12f; if (blockIdx.x) g_sw2 = sc; else g_sw1 = sc; }
    }
}

// NCHW fp32 -> quantized bf16 into PADDED NHWC (zero ring untouched)
__global__ void k_quant_x(const float* __restrict__ x) {
    __shared__ __nv_bfloat16 t[CC][121];
    int n = blockIdx.y, hw0 = blockIdx.x * 112;
    float qs = 127.f / (__uint_as_float(g_sx_bits) + 1e-12f);
    for (int i = threadIdx.x; i < CC*112; i += blockDim.x) {
        int c = i / 112, p = i % 112;
        float v = x[(size_t)(n*CC + c)*HWS + hw0 + p];
        int qi = __float2int_rn(v * qs);
        qi = max(-127, min(127, qi));
        t[c][p] = __float2bfloat16_rn((float)qi);   // exact for |qi|<=127
    }
    __syncthreads();
    __nv_bfloat16* abase = g_apad + (size_t)GUARD*CC;
    for (int i = threadIdx.x; i < 112*64; i += blockDim.x) {
        int p = i / 64, cq = i % 64;
        int lidx = hw0 + p, h = lidx / WW, w = lidx % WW;
        __nv_bfloat162 v2; v2.x = t[2*cq][p]; v2.y = t[2*cq+1][p];
        *reinterpret_cast<__nv_bfloat162*>(
            abase + ((size_t)n*PIMG + (h+1)*HP + (w+1))*CC + 2*cq) = v2;
    }
}

// OIHW fp32 -> [tap][co][ci] quantized bf16
__global__ void k_quant_w(const float* __restrict__ w1, const float* __restrict__ w2) {
    int t = blockIdx.y;
    const float* w = t ? w2 : w1;
    __nv_bfloat16* o = t ? g_w2q : g_w1q;
    float q = 127.f / (t ? g_sw2 : g_sw1);
    for (int i = blockIdx.x*blockDim.x + threadIdx.x; i < CC*9*CC; i += gridDim.x*blockDim.x) {
        int co = i / (9*CC), r = i % (9*CC), tap = r / CC, ci = r % CC;
        float v = w[(co*CC + ci)*9 + tap];
        int qi = __float2int_rn(v * q);
        qi = max(-127, min(127, qi));
        o[((size_t)tap*CC + co)*CC + ci] = __float2bfloat16_rn((float)qi);
    }
}

// copy one tap's A + B bf16 tiles to smem with XOR-16B swizzle (cp.async)
__device__ __forceinline__ void prefetch_tap(const __nv_bfloat16* abase, const __nv_bfloat16* wl,
                                             int tap, uint32_t smA, uint32_t smB, int tid) {
    int tapoff = ((tap/3) - 1)*HP + (tap%3) - 1;
    const char* asrc = (const char*)(abase + (ptrdiff_t)tapoff * CC);
    #pragma unroll
    for (int i = tid; i < 2048; i += 128) {
        int row = i >> 4, c = i & 15;
        cpasync16(smA + row*256 + ((c ^ (row & 7)) << 4), asrc + row*256 + c*16);
    }
    const char* bsrc = (const char*)(wl + (size_t)tap*CC*CC);
    #pragma unroll
    for (int i = tid; i < 2048; i += 128) {
        int row = i >> 4, c = i & 15;
        cpasync16(smB + row*256 + ((c ^ (row & 7)) << 4), bsrc + row*256 + c*16);
    }
    CP_COMMIT();
}

// implicit-GEMM 3x3 conv via bf16 HMMA: CTA = 128 px x 128 co, 4 warps of 64x64.
// Epilogue additionally produces per-CTA BN partials (sum/sumsq/min/max per channel).
__global__ void __launch_bounds__(128, 1) k_conv(int layer) {
    extern __shared__ char sm[];
    uint32_t smb = smem_u32(sm);
    float*    st_sum = reinterpret_cast<float*>(sm + 4*TAPB);
    float*    st_sq  = st_sum + CC;
    unsigned* st_mx  = reinterpret_cast<unsigned*>(st_sq + CC);
    unsigned* st_mn  = st_mx + CC;

    int tid = threadIdx.x, lane = tid & 31, wid = tid >> 5;
    int img = blockIdx.x / NTILE, tile = blockIdx.x % NTILE;
    int warpM = wid & 1, warpN = wid >> 1;    // 2x2 warps, each 64 px x 64 co

    const __nv_bfloat16* abase = g_apad + (size_t)GUARD*CC + ((size_t)img*PIMG + tile*128)*CC;
    const __nv_bfloat16* wl = layer ? g_w2q : g_w1q;

    if (tid < CC) {
        st_sum[tid] = 0.f; st_sq[tid] = 0.f;
        st_mx[tid] = 0u;   st_mn[tid] = 0xFFFFFFFFu;
    }

    float acc[4][8][4] = {};

    prefetch_tap(abase, wl, 0, smb, smb + TAPB, tid);

    int rowA0 = warpM*64 + (lane & 15);
    int rowB0 = warpN*64 + (lane & 7) + ((lane >> 4) << 3);
    int chA_add = lane >> 4;        // +0/+1 16B chunk within k-step
    int chB_add = (lane >> 3) & 1;

    for (int t = 0; t < 9; t++) {
        __syncthreads();
        if (t < 8) {
            uint32_t s = smb + ((t+1) & 1)*2*TAPB;
            prefetch_tap(abase, wl, t+1, s, s + TAPB, tid);
            CP_WAIT1();
        } else {
            CP_WAIT0();
        }
        __syncthreads();

        uint32_t smA = smb + (t & 1)*2*TAPB;
        uint32_t smB = smA + TAPB;

        #pragma unroll
        for (int ks = 0; ks < 8; ks++) {         // K=16 bf16 per step
            uint32_t a[4][4];
            #pragma unroll
            for (int mf = 0; mf < 4; mf++) {
                int r = rowA0 + mf*16;
                int ch = 2*ks + chA_add;
                ldsm_x4(a[mf][0], a[mf][1], a[mf][2], a[mf][3],
                        smA + r*256 + ((ch ^ (r & 7)) << 4));
            }
            uint32_t b[8][2];
            #pragma unroll
            for (int nf2 = 0; nf2 < 4; nf2++) {
                int r = rowB0 + nf2*16;
                int ch = 2*ks + chB_add;
                uint32_t b0, b1, b2, b3;
                ldsm_x4(b0, b1, b2, b3, smB + r*256 + ((ch ^ (r & 7)) << 4));
                b[nf2*2][0] = b0; b[nf2*2][1] = b1;
                b[nf2*2+1][0] = b2; b[nf2*2+1][1] = b3;
            }
            #pragma unroll
            for (int mf = 0; mf < 4; mf++)
                #pragma unroll
                for (int nf = 0; nf < 8; nf++)
                    mma_bf16(acc[mf][nf], a[mf], b[nf]);
        }
    }

    float sact  = layer ? g_sa1 : (__uint_as_float(g_sx_bits) + 1e-12f);
    float sw    = layer ? g_sw2 : g_sw1;
    float scale = sact * sw * (1.f/16129.f);

    // store valid pixels
    #pragma unroll
    for (int mf = 0; mf < 4; mf++) {
        int rl = warpM*64 + mf*16 + (lane >> 2);
        #pragma unroll
        for (int half = 0; half < 2; half++) {
            int pixl = tile*128 + rl + half*8;
            int hp = pixl / HP, wp = pixl % HP;
            if (hp >= 1 && hp <= HH && wp >= 1 && wp <= WW) {
                float* dst = g_y + ((size_t)img*HWS + (hp-1)*WW + (wp-1))*CC;
                #pragma unroll
                for (int nf = 0; nf < 8; nf++) {
                    int col = warpN*64 + nf*8 + (lane & 3)*2;
                    float2 v;
                    v.x = acc[mf][nf][half*2+0] * scale;
                    v.y = acc[mf][nf][half*2+1] * scale;
                    *reinterpret_cast<float2*>(dst + col) = v;
                }
            }
        }
    }

    // per-CTA BN partials: register-reduce over this thread's 8 row-instances,
    // then shared atomics (fp add jitter ~1e-7 rel; min/max order-invariant)
    #pragma unroll
    for (int nf = 0; nf < 8; nf++) {
        #pragma unroll
        for (int sc = 0; sc < 2; sc++) {
            float s = 0.f, qq = 0.f, mn = 3.4e38f, mx = -3.4e38f;
            int cnt = 0;
            #pragma unroll
            for (int mf = 0; mf < 4; mf++) {
                #pragma unroll
                for (int half = 0; half < 2; half++) {
                    int pixl = tile*128 + warpM*64 + mf*16 + (lane >> 2) + half*8;
                    int hp = pixl / HP, wp = pixl % HP;
                    if (hp >= 1 && hp <= HH && wp >= 1 && wp <= WW) {
                        float v = acc[mf][nf][half*2+sc] * scale;
                        s += v; qq += v*v;
                        mn = fminf(mn, v); mx = fmaxf(mx, v);
                        cnt++;
                    }
                }
            }
            if (cnt) {
                int col = warpN*64 + nf*8 + (lane & 3)*2 + sc;
                atomicAdd(&st_sum[col], s);
                atomicAdd(&st_sq[col], qq);
                atomicMax(&st_mx[col], encf(mx));
                atomicMin(&st_mn[col], encf(mn));
            }
        }
    }
    __syncthreads();
    if (tid < CC) {
        int o = blockIdx.x*CC + tid;
        g_psum[o]  = st_sum[tid];
        g_psum2[o] = st_sq[tid];
        g_pmax[o]  = decf(st_mx[tid]);   // NaN if CTA had no valid pixel (fmaxf-safe)
        g_pmin[o]  = decf(st_mn[tid]);
    }
}

// final reduce over NCTA partials: mean/rstd per channel; act scale via min/max trick
__global__ void k_bnfin(const float* __restrict__ gamma, const float* __restrict__ beta,
                        int layer, int doAct) {
    int tid = threadIdx.x;
    int c = tid & 127, q = tid >> 7;
    double s = 0.0, s2 = 0.0;
    float mn = 3.4e38f, mx = -3.4e38f;
    for (int b = q; b < NCTA; b += 4) {
        int o = b*CC + c;
        s += (double)g_psum[o]; s2 += (double)g_psum2[o];
        mn = fminf(mn, g_pmin[o]); mx = fmaxf(mx, g_pmax[o]);
    }
    __shared__ double ss[512], ss2[512];
    __shared__ float  smn[512], smx[512];
    __shared__ float  actmax[CC];
    ss[tid] = s; ss2[tid] = s2; smn[tid] = mn; smx[tid] = mx;
    __syncthreads();
    if (q == 0) {
        #pragma unroll
        for (int k = 1; k < 4; k++) {
            s += ss[k*128 + c]; s2 += ss2[k*128 + c];
            mn = fminf(mn, smn[k*128 + c]); mx = fmaxf(mx, smx[k*128 + c]);
        }
        double mean = s / (double)NPIX;
        double var  = s2 / (double)NPIX - mean*mean;
        float rstd = (float)(1.0 / sqrt(var + 1e-5));
        float A  = gamma[c] * rstd;
        float Bc = beta[c] - (float)mean * A;
        g_bnA[layer*CC + c] = A;
        g_bnB[layer*CC + c] = Bc;
        actmax[c] = fmaxf(fmaxf(mx*A + Bc, 0.f), fmaxf(mn*A + Bc, 0.f));
    }
    __syncthreads();
    if (doAct && tid == 0) {
        float m = 0.f;
        for (int k = 0; k < CC; k++) m = fmaxf(m, actmax[k]);
        g_sa1 = m + 1e-12f;
    }
}

// bn1 + relu + quantize -> padded bf16 activations for layer 2
__global__ void k_bnq() {
    int i4 = blockIdx.x*blockDim.x + threadIdx.x;
    if (i4 >= NELT/4) return;
    float qa = 127.f / g_sa1;
    float4 v = reinterpret_cast<const float4*>(g_y)[i4];
    int p = i4 >> 5, cb = (i4 & 31)*4;
    float t0 = fmaxf(v.x*g_bnA[cb+0] + g_bnB[cb+0], 0.f);
    float t1 = fmaxf(v.y*g_bnA[cb+1] + g_bnB[cb+1], 0.f);
    float t2 = fmaxf(v.z*g_bnA[cb+2] + g_bnB[cb+2], 0.f);
    float t3 = fmaxf(v.w*g_bnA[cb+3] + g_bnB[cb+3], 0.f);
    int q0 = max(-127, min(127, __float2int_rn(t0*qa)));
    int q1 = max(-127, min(127, __float2int_rn(t1*qa)));
    int q2 = max(-127, min(127, __float2int_rn(t2*qa)));
    int q3 = max(-127, min(127, __float2int_rn(t3*qa)));
    int n = p / HWS, r = p % HWS, h = r / WW, w = r % WW;
    __nv_bfloat16* abase = g_apad + (size_t)GUARD*CC;
    __nv_bfloat162 lo, hi;
    lo.x = __float2bfloat16_rn((float)q0); lo.y = __float2bfloat16_rn((float)q1);
    hi.x = __float2bfloat16_rn((float)q2); hi.y = __float2bfloat16_rn((float)q3);
    uint2 pk;
    pk.x = *reinterpret_cast<uint32_t*>(&lo);
    pk.y = *reinterpret_cast<uint32_t*>(&hi);
    *reinterpret_cast<uint2*>(abase + ((size_t)n*PIMG + (h+1)*HP + (w+1))*CC + cb) = pk;
}

// bn2 + identity add + relu, NHWC -> NCHW via smem transpose
__global__ void k_final(const float* __restrict__ x, float* __restrict__ out) {
    __shared__ float t[CC][57];
    int n = blockIdx.y, row = blockIdx.x;
    int hw0 = row * WW;
    for (int i = threadIdx.x; i < WW*CC; i += blockDim.x) {
        int c = i & 127, p = i >> 7;
        t[c][p] = g_y[(size_t)(n*HWS + hw0 + p)*CC + c];
    }
    __syncthreads();
    for (int i = threadIdx.x; i < CC*WW; i += blockDim.x) {
        int c = i / WW, p = i % WW;
        size_t gi = (size_t)(n*CC + c)*HWS + hw0 + p;
        float v = t[c][p]*g_bnA[CC + c] + g_bnB[CC + c] + x[gi];
        out[gi] = fmaxf(v, 0.f);
    }
}

// ---------------------------------------------------------------- launcher --
extern "C" void kernel_launch(void* const* d_in, const int* in_sizes, int n_in,
                              void* d_out, int out_size) {
    const float* x      = (const float*)d_in[0];
    const float* w1     = (const float*)d_in[1];
    const float* gamma1 = (const float*)d_in[2];
    const float* beta1  = (const float*)d_in[3];
    const float* w2     = (const float*)d_in[4];
    const float* gamma2 = (const float*)d_in[5];
    const float* beta2  = (const float*)d_in[6];
    float* out = (float*)d_out;
    (void)in_sizes; (void)n_in; (void)out_size;

    cudaFuncSetAttribute(k_conv, cudaFuncAttributeMaxDynamicSharedMemorySize, CONV_SMEM);

    k_zero<<<1, 1>>>();
    k_absmax_x<<<1024, 256>>>(x);
    k_absmax_w<<<2, 1024>>>(w1, w2);
    k_quant_x<<<dim3(28, BB), 256>>>(x);
    k_quant_w<<<dim3(64, 2), 256>>>(w1, w2);

    k_conv<<<NCTA, 128, CONV_SMEM>>>(0);
    k_bnfin<<<1, 512>>>(gamma1, beta1, 0, 1);
    k_bnq<<<(NELT/4 + 255)/256, 256>>>();

    k_conv<<<NCTA, 128, CONV_SMEM>>>(1);
    k_bnfin<<<1, 512>>>(gamma2, beta2, 1, 0);
    k_final<<<dim3(HH, BB), 256>>>(x, out);
}

// round 14
// speedup vs baseline: 1.4665x; 1.4665x over previous
#include <cuda_runtime.h>
#include <cuda_bf16.h>
#include <cstdint>

#define BB   32
#define CC   128
#define HH   56
#define WW   56
#define HWS  (HH*WW)          // 3136
#define NPIX (BB*HWS)         // 100352
#define NELT (NPIX*CC)        // 12845056

// padded spatial layout: 58x58 per image (zero ring) + guard rows front/back
#define HP    58
#define PIMG  (HP*HP)         // 3364
#define GUARD 192             // guard rows (128 ch each) for halo over/underflow
#define MTILE 192             // output pixels per CTA
#define NTILE 18              // ceil(3364/192)
#define NCTA  (BB*NTILE)      // 576 conv CTAs (also stats slots)

#define HALO_ROWS 320         // 310 used: MTILE + 2*59
#define HALOB (HALO_ROWS*256) // 81920 B (bf16 rows of 256B)
#define BSTG  32768           // one 128co x 128ci bf16 weight tile
#define CONV_SMEM (HALOB + 2*BSTG + 2048)   // 149504

// ----------------------------- scratch (device globals: no runtime allocs) --
__device__ __nv_bfloat16 g_apad[((size_t)GUARD + (size_t)BB*PIMG + GUARD) * CC]; // padded acts bf16
__device__ float         g_y[NELT];           // conv output, compact NHWC fp32
__device__ __nv_bfloat16 g_w1q[9*CC*CC];      // [tap][co][ci] bf16 (quantized ints)
__device__ __nv_bfloat16 g_w2q[9*CC*CC];
__device__ unsigned      g_sx_bits;
__device__ float         g_sw1, g_sw2, g_sa1;
__device__ float         g_bnA[2*CC], g_bnB[2*CC];
__device__ float         g_psum[NCTA*CC], g_psum2[NCTA*CC];
__device__ float         g_pmin[NCTA*CC], g_pmax[NCTA*CC];

// --------------------------------------------------------------- PTX glue --
__device__ __forceinline__ uint32_t smem_u32(const void* p) {
    uint32_t a;
    asm("{ .reg .u64 t; cvta.to.shared.u64 t, %1; cvt.u32.u64 %0, t; }" : "=r"(a) : "l"(p));
    return a;
}
__device__ __forceinline__ void cpasync16(uint32_t dst, const void* src) {
    asm volatile("cp.async.cg.shared.global [%0], [%1], 16;" :: "r"(dst), "l"(src));
}
#define CP_COMMIT() asm volatile("cp.async.commit_group;" ::: "memory")
#define CP_WAIT0()  asm volatile("cp.async.wait_group 0;" ::: "memory")
#define CP_WAIT1()  asm volatile("cp.async.wait_group 1;" ::: "memory")

__device__ __forceinline__ void ldsm_x4(uint32_t& r0, uint32_t& r1, uint32_t& r2, uint32_t& r3,
                                        uint32_t addr) {
    asm volatile("ldmatrix.sync.aligned.m8n8.x4.shared.b16 {%0,%1,%2,%3}, [%4];"
                 : "=r"(r0), "=r"(r1), "=r"(r2), "=r"(r3) : "r"(addr));
}
__device__ __forceinline__ void mma_bf16(float* c, const uint32_t* a, const uint32_t* b) {
    asm volatile("mma.sync.aligned.m16n8k16.row.col.f32.bf16.bf16.f32 "
                 "{%0,%1,%2,%3}, {%4,%5,%6,%7}, {%8,%9}, {%0,%1,%2,%3};"
                 : "+f"(c[0]), "+f"(c[1]), "+f"(c[2]), "+f"(c[3])
                 : "r"(a[0]), "r"(a[1]), "r"(a[2]), "r"(a[3]), "r"(b[0]), "r"(b[1]));
}
// order-invariant float<->uint encodings for atomic min/max
__device__ __forceinline__ unsigned encf(float f) {
    unsigned b = __float_as_uint(f);
    return (b & 0x80000000u) ? ~b : (b | 0x80000000u);
}
__device__ __forceinline__ float decf(unsigned u) {
    return __uint_as_float((u & 0x80000000u) ? (u & 0x7FFFFFFFu) : ~u);
}

// ----------------------------------------------------------------- helpers --
__global__ void k_zero() { g_sx_bits = 0u; }

__global__ void k_absmax_x(const float* __restrict__ x) {
    float m = 0.f;
    for (int i = blockIdx.x*blockDim.x + threadIdx.x; i < NELT; i += gridDim.x*blockDim.x)
        m = fmaxf(m, fabsf(x[i]));
    #pragma unroll
    for (int o = 16; o; o >>= 1) m = fmaxf(m, __shfl_xor_sync(0xffffffffu, m, o));
    __shared__ float s[32];
    int w = threadIdx.x >> 5, l = threadIdx.x & 31;
    if (l == 0) s[w] = m;
    __syncthreads();
    if (w == 0) {
        m = (l < (blockDim.x >> 5)) ? s[l] : 0.f;
        #pragma unroll
        for (int o = 16; o; o >>= 1) m = fmaxf(m, __shfl_xor_sync(0xffffffffu, m, o));
        if (l == 0) atomicMax(&g_sx_bits, __float_as_uint(m));
    }
}

__global__ void k_absmax_w(const float* __restrict__ w1, const float* __restrict__ w2) {
    const float* w = blockIdx.x ? w2 : w1;
    float m = 0.f;
    for (int i = threadIdx.x; i < CC*CC*9; i += blockDim.x) m = fmaxf(m, fabsf(w[i]));
    #pragma unroll
    for (int o = 16; o; o >>= 1) m = fmaxf(m, __shfl_xor_sync(0xffffffffu, m, o));
    __shared__ float s[32];
    int wi = threadIdx.x >> 5, l = threadIdx.x & 31;
    if (l == 0) s[wi] = m;
    __syncthreads();
    if (wi == 0) {
        m = (l < (blockDim.x >> 5)) ? s[l] : 0.f;
        #pragma unroll
        for (int o = 16; o; o >>= 1) m = fmaxf(m, __shfl_xor_sync(0xffffffffu, m, o));
        if (l == 0) { float sc = m + 1e-12f; if (blockIdx.x) g_sw2 = sc; else g_sw1 = sc; }
    }
}

// NCHW fp32 -> quantized bf16 into PADDED NHWC (zero ring untouched)
__global__ void k_quant_x(const float* __restrict__ x) {
    __shared__ __nv_bfloat16 t[CC][121];
    int n = blockIdx.y, hw0 = blockIdx.x * 112;
    float qs = 127.f / (__uint_as_float(g_sx_bits) + 1e-12f);
    for (int i = threadIdx.x; i < CC*112; i += blockDim.x) {
        int c = i / 112, p = i % 112;
        float v = x[(size_t)(n*CC + c)*HWS + hw0 + p];
        int qi = __float2int_rn(v * qs);
        qi = max(-127, min(127, qi));
        t[c][p] = __float2bfloat16_rn((float)qi);   // exact for |qi|<=127
    }
    __syncthreads();
    __nv_bfloat16* abase = g_apad + (size_t)GUARD*CC;
    for (int i = threadIdx.x; i < 112*64; i += blockDim.x) {
        int p = i / 64, cq = i % 64;
        int lidx = hw0 + p, h = lidx / WW, w = lidx % WW;
        __nv_bfloat162 v2; v2.x = t[2*cq][p]; v2.y = t[2*cq+1][p];
        *reinterpret_cast<__nv_bfloat162*>(
            abase + ((size_t)n*PIMG + (h+1)*HP + (w+1))*CC + 2*cq) = v2;
    }
}

// OIHW fp32 -> [tap][co][ci] quantized bf16
__global__ void k_quant_w(const float* __restrict__ w1, const float* __restrict__ w2) {
    int t = blockIdx.y;
    const float* w = t ? w2 : w1;
    __nv_bfloat16* o = t ? g_w2q : g_w1q;
    float q = 127.f / (t ? g_sw2 : g_sw1);
    for (int i = blockIdx.x*blockDim.x + threadIdx.x; i < CC*9*CC; i += gridDim.x*blockDim.x) {
        int co = i / (9*CC), r = i % (9*CC), tap = r / CC, ci = r % CC;
        float v = w[(co*CC + ci)*9 + tap];
        int qi = __float2int_rn(v * q);
        qi = max(-127, min(127, qi));
        o[((size_t)tap*CC + co)*CC + ci] = __float2bfloat16_rn((float)qi);
    }
}

// copy one tap's B (weights) tile to a smem stage with XOR-16B swizzle
__device__ __forceinline__ void prefetch_B(const __nv_bfloat16* wl, int tap,
                                           uint32_t smB, int tid) {
    const char* bsrc = (const char*)(wl + (size_t)tap*CC*CC);
    #pragma unroll
    for (int i = tid; i < 2048; i += 384) {
        int row = i >> 4, c = i & 15;
        cpasync16(smB + row*256 + ((c ^ (row & 7)) << 4), bsrc + row*256 + c*16);
    }
    CP_COMMIT();
}

// implicit-GEMM 3x3 conv via bf16 HMMA with SMEM-RESIDENT A HALO.
// CTA = 192 padded px x 128 co; 12 warps (3M x 4N) of 64x32 tiles.
// The 9 tap A-tiles are row-shifted views into one 310-row halo loaded once.
// Epilogue fuses per-CTA BN partials (sum/sumsq/min/max per channel).
__global__ void __launch_bounds__(384, 1) k_conv(int layer) {
    extern __shared__ char sm[];
    uint32_t smHalo = smem_u32(sm);
    uint32_t smB0   = smHalo + HALOB;
    float*    st_sum = reinterpret_cast<float*>(sm + HALOB + 2*BSTG);
    float*    st_sq  = st_sum + CC;
    unsigned* st_mx  = reinterpret_cast<unsigned*>(st_sq + CC);
    unsigned* st_mn  = st_mx + CC;

    int tid = threadIdx.x, lane = tid & 31, wid = tid >> 5;
    int img = blockIdx.x / NTILE, tile = blockIdx.x % NTILE;
    int warpM = wid % 3, warpN = wid / 3;    // 3 x 4 warps, each 64 px x 32 co

    const __nv_bfloat16* wl = layer ? g_w2q : g_w1q;

    if (tid < CC) {
        st_sum[tid] = 0.f; st_sq[tid] = 0.f;
        st_mx[tid] = 0u;   st_mn[tid] = 0xFFFFFFFFu;
    }

    // halo source: padded rows [tile*MTILE - 59, +310) of this image
    {
        const char* hsrc = (const char*)(g_apad + (size_t)GUARD*CC
                          + ((ptrdiff_t)img*PIMG + tile*MTILE - 59)*CC);
        #pragma unroll
        for (int i = tid; i < 4960; i += 384) {     // 310 rows x 16 chunks
            int row = i >> 4, c = i & 15;
            cpasync16(smHalo + row*256 + ((c ^ (row & 7)) << 4), hsrc + row*256 + c*16);
        }
        CP_COMMIT();
    }
    prefetch_B(wl, 0, smB0, tid);

    float acc[4][4][4] = {};

    int laneA = lane & 15;
    int chA_add = lane >> 4;
    int rowB0 = warpN*32 + (lane & 7) + ((lane >> 4) << 3);
    int chB_add = (lane >> 3) & 1;

    for (int t = 0; t < 9; t++) {
        __syncthreads();
        if (t < 8) {
            prefetch_B(wl, t+1, smB0 + ((t+1) & 1)*BSTG, tid);
            CP_WAIT1();     // halo + B_t complete
        } else {
            CP_WAIT0();
        }
        __syncthreads();

        int tapBase = 59 + (t/3 - 1)*HP + (t%3 - 1) + warpM*64 + laneA;
        uint32_t smBt = smB0 + (t & 1)*BSTG;

        #pragma unroll
        for (int ks = 0; ks < 8; ks++) {         // K=16 bf16 per step
            uint32_t a[4][4];
            #pragma unroll
            for (int mf = 0; mf < 4; mf++) {
                int r = tapBase + mf*16;
                int ch = 2*ks + chA_add;
                ldsm_x4(a[mf][0], a[mf][1], a[mf][2], a[mf][3],
                        smHalo + r*256 + ((ch ^ (r & 7)) << 4));
            }
            uint32_t b[4][2];
            #pragma unroll
            for (int nf2 = 0; nf2 < 2; nf2++) {
                int r = rowB0 + nf2*16;
                int ch = 2*ks + chB_add;
                uint32_t b0, b1, b2, b3;
                ldsm_x4(b0, b1, b2, b3, smBt + r*256 + ((ch ^ (r & 7)) << 4));
                b[nf2*2][0] = b0; b[nf2*2][1] = b1;
                b[nf2*2+1][0] = b2; b[nf2*2+1][1] = b3;
            }
            #pragma unroll
            for (int mf = 0; mf < 4; mf++)
                #pragma unroll
                for (int nf = 0; nf < 4; nf++)
                    mma_bf16(acc[mf][nf], a[mf], b[nf]);
        }
    }

    float sact  = layer ? g_sa1 : (__uint_as_float(g_sx_bits) + 1e-12f);
    float sw    = layer ? g_sw2 : g_sw1;
    float scale = sact * sw * (1.f/16129.f);

    // store valid pixels
    #pragma unroll
    for (int mf = 0; mf < 4; mf++) {
        int rl = warpM*64 + mf*16 + (lane >> 2);
        #pragma unroll
        for (int half = 0; half < 2; half++) {
            int pixl = tile*MTILE + rl + half*8;
            int hp = pixl / HP, wp = pixl % HP;
            if (hp >= 1 && hp <= HH && wp >= 1 && wp <= WW) {
                float* dst = g_y + ((size_t)img*HWS + (hp-1)*WW + (wp-1))*CC;
                #pragma unroll
                for (int nf = 0; nf < 4; nf++) {
                    int col = warpN*32 + nf*8 + (lane & 3)*2;
                    float2 v;
                    v.x = acc[mf][nf][half*2+0] * scale;
                    v.y = acc[mf][nf][half*2+1] * scale;
                    *reinterpret_cast<float2*>(dst + col) = v;
                }
            }
        }
    }

    // per-CTA BN partials: register-reduce over this thread's 8 row-instances,
    // then shared atomics (fp add jitter ~1e-7 rel; min/max order-invariant)
    #pragma unroll
    for (int nf = 0; nf < 4; nf++) {
        #pragma unroll
        for (int sc = 0; sc < 2; sc++) {
            float s = 0.f, qq = 0.f, mn = 3.4e38f, mx = -3.4e38f;
            int cnt = 0;
            #pragma unroll
            for (int mf = 0; mf < 4; mf++) {
                #pragma unroll
                for (int half = 0; half < 2; half++) {
                    int pixl = tile*MTILE + warpM*64 + mf*16 + (lane >> 2) + half*8;
                    int hp = pixl / HP, wp = pixl % HP;
                    if (hp >= 1 && hp <= HH && wp >= 1 && wp <= WW) {
                        float v = acc[mf][nf][half*2+sc] * scale;
                        s += v; qq += v*v;
                        mn = fminf(mn, v); mx = fmaxf(mx, v);
                        cnt++;
                    }
                }
            }
            if (cnt) {
                int col = warpN*32 + nf*8 + (lane & 3)*2 + sc;
                atomicAdd(&st_sum[col], s);
                atomicAdd(&st_sq[col], qq);
                atomicMax(&st_mx[col], encf(mx));
                atomicMin(&st_mn[col], encf(mn));
            }
        }
    }
    __syncthreads();
    if (tid < CC) {
        int o = blockIdx.x*CC + tid;
        g_psum[o]  = st_sum[tid];
        g_psum2[o] = st_sq[tid];
        g_pmax[o]  = decf(st_mx[tid]);
        g_pmin[o]  = decf(st_mn[tid]);
    }
}

// final reduce over NCTA partials: mean/rstd per channel; act scale via min/max trick
__global__ void k_bnfin(const float* __restrict__ gamma, const float* __restrict__ beta,
                        int layer, int doAct) {
    int tid = threadIdx.x;
    int c = tid & 127, q = tid >> 7;
    double s = 0.0, s2 = 0.0;
    float mn = 3.4e38f, mx = -3.4e38f;
    for (int b = q; b < NCTA; b += 4) {
        int o = b*CC + c;
        s += (double)g_psum[o]; s2 += (double)g_psum2[o];
        mn = fminf(mn, g_pmin[o]); mx = fmaxf(mx, g_pmax[o]);
    }
    __shared__ double ss[512], ss2[512];
    __shared__ float  smn[512], smx[512];
    __shared__ float  actmax[CC];
    ss[tid] = s; ss2[tid] = s2; smn[tid] = mn; smx[tid] = mx;
    __syncthreads();
    if (q == 0) {
        #pragma unroll
        for (int k = 1; k < 4; k++) {
            s += ss[k*128 + c]; s2 += ss2[k*128 + c];
            mn = fminf(mn, smn[k*128 + c]); mx = fmaxf(mx, smx[k*128 + c]);
        }
        double mean = s / (double)NPIX;
        double var  = s2 / (double)NPIX - mean*mean;
        float rstd = (float)(1.0 / sqrt(var + 1e-5));
        float A  = gamma[c] * rstd;
        float Bc = beta[c] - (float)mean * A;
        g_bnA[layer*CC + c] = A;
        g_bnB[layer*CC + c] = Bc;
        actmax[c] = fmaxf(fmaxf(mx*A + Bc, 0.f), fmaxf(mn*A + Bc, 0.f));
    }
    __syncthreads();
    if (doAct && tid == 0) {
        float m = 0.f;
        for (int k = 0; k < CC; k++) m = fmaxf(m, actmax[k]);
        g_sa1 = m + 1e-12f;
    }
}

// bn1 + relu + quantize -> padded bf16 activations for layer 2
__global__ void k_bnq() {
    int i4 = blockIdx.x*blockDim.x + threadIdx.x;
    if (i4 >= NELT/4) return;
    float qa = 127.f / g_sa1;
    float4 v = reinterpret_cast<const float4*>(g_y)[i4];
    int p = i4 >> 5, cb = (i4 & 31)*4;
    float t0 = fmaxf(v.x*g_bnA[cb+0] + g_bnB[cb+0], 0.f);
    float t1 = fmaxf(v.y*g_bnA[cb+1] + g_bnB[cb+1], 0.f);
    float t2 = fmaxf(v.z*g_bnA[cb+2] + g_bnB[cb+2], 0.f);
    float t3 = fmaxf(v.w*g_bnA[cb+3] + g_bnB[cb+3], 0.f);
    int q0 = max(-127, min(127, __float2int_rn(t0*qa)));
    int q1 = max(-127, min(127, __float2int_rn(t1*qa)));
    int q2 = max(-127, min(127, __float2int_rn(t2*qa)));
    int q3 = max(-127, min(127, __float2int_rn(t3*qa)));
    int n = p / HWS, r = p % HWS, h = r / WW, w = r % WW;
    __nv_bfloat16* abase = g_apad + (size_t)GUARD*CC;
    __nv_bfloat162 lo, hi;
    lo.x = __float2bfloat16_rn((float)q0); lo.y = __float2bfloat16_rn((float)q1);
    hi.x = __float2bfloat16_rn((float)q2); hi.y = __float2bfloat16_rn((float)q3);
    uint2 pk;
    pk.x = *reinterpret_cast<uint32_t*>(&lo);
    pk.y = *reinterpret_cast<uint32_t*>(&hi);
    *reinterpret_cast<uint2*>(abase + ((size_t)n*PIMG + (h+1)*HP + (w+1))*CC + cb) = pk;
}

// bn2 + identity add + relu, NHWC -> NCHW via smem transpose
__global__ void k_final(const float* __restrict__ x, float* __restrict__ out) {
    __shared__ float t[CC][57];
    int n = blockIdx.y, row = blockIdx.x;
    int hw0 = row * WW;
    for (int i = threadIdx.x; i < WW*CC; i += blockDim.x) {
        int c = i & 127, p = i >> 7;
        t[c][p] = g_y[(size_t)(n*HWS + hw0 + p)*CC + c];
    }
    __syncthreads();
    for (int i = threadIdx.x; i < CC*WW; i += blockDim.x) {
        int c = i / WW, p = i % WW;
        size_t gi = (size_t)(n*CC + c)*HWS + hw0 + p;
        float v = t[c][p]*g_bnA[CC + c] + g_bnB[CC + c] + x[gi];
        out[gi] = fmaxf(v, 0.f);
    }
}

// ---------------------------------------------------------------- launcher --
extern "C" void kernel_launch(void* const* d_in, const int* in_sizes, int n_in,
                              void* d_out, int out_size) {
    const float* x      = (const float*)d_in[0];
    const float* w1     = (const float*)d_in[1];
    const float* gamma1 = (const float*)d_in[2];
    const float* beta1  = (const float*)d_in[3];
    const float* w2     = (const float*)d_in[4];
    const float* gamma2 = (const float*)d_in[5];
    const float* beta2  = (const float*)d_in[6];
    float* out = (float*)d_out;
    (void)in_sizes; (void)n_in; (void)out_size;

    cudaFuncSetAttribute(k_conv, cudaFuncAttributeMaxDynamicSharedMemorySize, CONV_SMEM);

    k_zero<<<1, 1>>>();
    k_absmax_x<<<1024, 256>>>(x);
    k_absmax_w<<<2, 1024>>>(w1, w2);
    k_quant_x<<<dim3(28, BB), 256>>>(x);
    k_quant_w<<<dim3(64, 2), 256>>>(w1, w2);

    k_conv<<<NCTA, 384, CONV_SMEM>>>(0);
    k_bnfin<<<1, 512>>>(gamma1, beta1, 0, 1);
    k_bnq<<<(NELT/4 + 255)/256, 256>>>();

    k_conv<<<NCTA, 384, CONV_SMEM>>>(1);
    k_bnfin<<<1, 512>>>(gamma2, beta2, 1, 0);
    k_final<<<dim3(HH, BB), 256>>>(x, out);
}